// round 14
// baseline (speedup 1.0000x reference)
#include <cuda_runtime.h>
#include <cuda_fp16.h>
#include <cstdint>

#define NTOK 2560
#define EDIM 512
#define NHEAD 8
#define HDIM 64
#define FFD 2048
#define VOC 32000
#define SEQ 80
#define NLAYER 4
#define BK 64

// ---------------- device scratch ----------------
__device__ float g_x[NTOK * EDIM];
__device__ float g_t512[3 * NTOK * EDIM];
__device__ float g_c[NLAYER * EDIM];
__device__ __half g_qkvh[NTOK * 3 * EDIM];
__device__ __half g_xh[NTOK * EDIM];
__device__ __half g_t512h[NTOK * EDIM];
__device__ __half g_h1h[NTOK * FFD];
__device__ __half g_wsain[NLAYER * 3 * EDIM * EDIM];
__device__ __half g_wsaout[NLAYER * EDIM * EDIM];
__device__ __half g_wff1[NLAYER * FFD * EDIM];
__device__ __half g_wff2[NLAYER * EDIM * FFD];
__device__ __half g_wout[(size_t)VOC * EDIM];

// ---------------- PTX helpers ----------------
__device__ __forceinline__ uint32_t smem_u32(const void* p) {
    uint32_t a;
    asm("{ .reg .u64 t; cvta.to.shared.u64 t, %1; cvt.u32.u64 %0, t; }" : "=r"(a) : "l"(p));
    return a;
}
__device__ __forceinline__ void cp16(uint32_t dst, const void* src) {
    asm volatile("cp.async.cg.shared.global [%0], [%1], 16;\n" :: "r"(dst), "l"(src));
}
__device__ __forceinline__ void cp_commit() { asm volatile("cp.async.commit_group;\n" ::: "memory"); }
template <int N>
__device__ __forceinline__ void cp_wait() { asm volatile("cp.async.wait_group %0;\n" :: "n"(N) : "memory"); }

__device__ __forceinline__ void gdc_launch() {
    asm volatile("griddepcontrol.launch_dependents;" ::: "memory");
}
__device__ __forceinline__ void gdc_wait() {
    asm volatile("griddepcontrol.wait;" ::: "memory");
}

__device__ __forceinline__ void ldsm4(uint32_t r[4], uint32_t addr) {
    asm volatile("ldmatrix.sync.aligned.m8n8.x4.shared.b16 {%0,%1,%2,%3},[%4];\n"
                 : "=r"(r[0]), "=r"(r[1]), "=r"(r[2]), "=r"(r[3]) : "r"(addr));
}
__device__ __forceinline__ void mma16816(float d[4], const uint32_t a[4], const uint32_t b[2]) {
    asm volatile(
        "mma.sync.aligned.m16n8k16.row.col.f32.f16.f16.f32 "
        "{%0,%1,%2,%3},{%4,%5,%6,%7},{%8,%9},{%0,%1,%2,%3};\n"
        : "+f"(d[0]), "+f"(d[1]), "+f"(d[2]), "+f"(d[3])
        : "r"(a[0]), "r"(a[1]), "r"(a[2]), "r"(a[3]), "r"(b[0]), "r"(b[1]));
}
__device__ __forceinline__ uint32_t swz(uint32_t off) { return off ^ ((off >> 3) & 0x70); }

// ---------------- pipelined fp16 HMMA GEMM, 128x128 CTA, split-K, PDL ----
#define BMt 128
#define BNt 128
#define NTN 8
#define NSTG 3
#define STB ((BMt + BNt) * 128)
#define SMEM_G (NSTG * STB)

__global__ void __launch_bounds__(256, 2) gemm_k(
    const __half* __restrict__ A, const __half* __restrict__ B,
    const float* __restrict__ bias, float* __restrict__ C, __half* __restrict__ Ch,
    int M, int N, int ldk, int ksp, int K, size_t csplit, int dorelu)
{
    extern __shared__ __align__(16) char sm[];
    const int tid = threadIdx.x, lane = tid & 31, warp = tid >> 5;
    const int bm = blockIdx.x * BMt, bn = blockIdx.y * BNt;
    const int z = blockIdx.z;
    const int k0 = z * ksp;
    const int klen = min(ksp, K - k0);
    const int S = klen / BK;
    const int wm = (warp & 3) * 32, wn = (warp >> 2) * (NTN * 8);
    const uint32_t smem0 = smem_u32(sm);

    float acc[2][NTN][4] = {};

    gdc_launch();

    // prologue part 1: B (weight) tiles — independent of predecessor output
#pragma unroll
    for (int s = 0; s < NSTG - 1; s++) {
        if (s < S) {
            uint32_t b0 = smem0 + (uint32_t)s * STB + (uint32_t)BMt * 128;
            int kabs = k0 + s * BK;
#pragma unroll
            for (int i = tid; i < BNt * 8; i += 256) {
                int r = i >> 3, cb = (i & 7) * 16;
                cp16(b0 + swz(r * 128 + cb),
                     (const char*)(B + (size_t)(bn + r) * ldk + kabs) + cb);
            }
        }
    }

    gdc_wait();

    // prologue part 2: A tiles + per-stage commits
#pragma unroll
    for (int s = 0; s < NSTG - 1; s++) {
        if (s < S) {
            uint32_t a0 = smem0 + (uint32_t)s * STB;
            int kabs = k0 + s * BK;
#pragma unroll
            for (int i = tid; i < BMt * 8; i += 256) {
                int r = i >> 3, cb = (i & 7) * 16;
                cp16(a0 + swz(r * 128 + cb),
                     (const char*)(A + (size_t)(bm + r) * ldk + kabs) + cb);
            }
        }
        cp_commit();
    }

    auto load_stage = [&](int st, int kabs) {
        uint32_t b0 = smem0 + (uint32_t)st * STB;
#pragma unroll
        for (int i = tid; i < (BMt + BNt) * 8; i += 256) {
            int r = i >> 3, cb = (i & 7) * 16;
            bool isA = r < BMt;
            int rr = isA ? r : r - BMt;
            uint32_t dst = b0 + (isA ? 0u : (uint32_t)BMt * 128) + swz(rr * 128 + cb);
            const char* p = isA ? (const char*)(A + (size_t)(bm + rr) * ldk + kabs) + cb
                                : (const char*)(B + (size_t)(bn + rr) * ldk + kabs) + cb;
            cp16(dst, p);
        }
    };

    const int lrow = lane & 7, seg = lane >> 3;
    for (int s = 0; s < S; s++) {
        cp_wait<NSTG - 2>();
        __syncthreads();
        if (s + NSTG - 1 < S) load_stage((s + NSTG - 1) % NSTG, k0 + (s + NSTG - 1) * BK);
        cp_commit();

        uint32_t b0 = smem0 + (uint32_t)(s % NSTG) * STB;
        uint32_t aA = b0, bB = b0 + (uint32_t)BMt * 128;

        uint32_t af[2][2][4];
#pragma unroll
        for (int mt = 0; mt < 2; mt++)
            ldsm4(af[0][mt], aA + swz((wm + mt * 16 + (lane & 15)) * 128 + (lane >> 4) * 16));

#pragma unroll
        for (int kc = 0; kc < 4; kc++) {
            const int kb = kc * 32;
            const int cur = kc & 1, nxt = cur ^ 1;
            uint32_t bfr[NTN][2];
#pragma unroll
            for (int nt = 0; nt < NTN; nt += 2) {
                uint32_t t4[4];
                ldsm4(t4, bB + swz((wn + (nt + (seg >> 1)) * 8 + lrow) * 128 +
                                   kb + (seg & 1) * 16));
                bfr[nt][0] = t4[0]; bfr[nt][1] = t4[1];
                bfr[nt + 1][0] = t4[2]; bfr[nt + 1][1] = t4[3];
            }
            if (kc < 3) {
                const int kb2 = kb + 32;
#pragma unroll
                for (int mt = 0; mt < 2; mt++)
                    ldsm4(af[nxt][mt], aA + swz((wm + mt * 16 + (lane & 15)) * 128 +
                                                kb2 + (lane >> 4) * 16));
            }
#pragma unroll
            for (int mt = 0; mt < 2; mt++)
#pragma unroll
                for (int nt = 0; nt < NTN; nt++)
                    mma16816(acc[mt][nt], af[cur][mt], bfr[nt]);
        }
    }

    float* Cz = C ? C + (size_t)z * csplit : nullptr;
#pragma unroll
    for (int mt = 0; mt < 2; mt++) {
#pragma unroll
        for (int nt = 0; nt < NTN; nt++) {
            int row = bm + wm + mt * 16 + (lane >> 2);
            int col = bn + wn + nt * 8 + (lane & 3) * 2;
            float b0 = (z == 0) ? bias[col] : 0.f;
            float b1 = (z == 0) ? bias[col + 1] : 0.f;
            float v0 = acc[mt][nt][0] + b0, v1 = acc[mt][nt][1] + b1;
            float v2 = acc[mt][nt][2] + b0, v3 = acc[mt][nt][3] + b1;
            if (dorelu) {
                v0 = fmaxf(v0, 0.f); v1 = fmaxf(v1, 0.f);
                v2 = fmaxf(v2, 0.f); v3 = fmaxf(v3, 0.f);
            }
            if (Cz) {
                *(float2*)&Cz[(size_t)row * N + col] = make_float2(v0, v1);
                *(float2*)&Cz[(size_t)(row + 8) * N + col] = make_float2(v2, v3);
            }
            if (Ch) {
                *(__half2*)&Ch[(size_t)row * N + col] = __floats2half2_rn(v0, v1);
                *(__half2*)&Ch[(size_t)(row + 8) * N + col] = __floats2half2_rn(v2, v3);
            }
        }
    }
}

// ---------------- fp32 -> fp16 weights ----------------
__global__ void convB_kernel(const float* __restrict__ s, __half* __restrict__ o, int n4)
{
    int i = blockIdx.x * blockDim.x + threadIdx.x;
    if (i >= n4) return;
    float4 v = ((const float4*)s)[i];
    ((__half2*)o)[2 * i]     = __floats2half2_rn(v.x, v.y);
    ((__half2*)o)[2 * i + 1] = __floats2half2_rn(v.z, v.w);
}

// ---------------- embedding gather ----------------
__global__ __launch_bounds__(256) void embed_kernel(
    const int* __restrict__ caps, const float* __restrict__ Win,
    const float* __restrict__ bin, const float* __restrict__ pos,
    float* __restrict__ x, __half* __restrict__ xh)
{
    int n = blockIdx.x;
    int tok = caps[n];
    int l = n % SEQ;
#pragma unroll
    for (int e = threadIdx.x; e < EDIM; e += 256) {
        float v = Win[(size_t)e * VOC + tok] + bin[e] + pos[l * EDIM + e];
        x[(size_t)n * EDIM + e] = v;
        xh[(size_t)n * EDIM + e] = __float2half_rn(v);
    }
}

// ---------------- causal self-attention: fp16 in, fp32 math, fp16 out, PDL -------
__global__ __launch_bounds__(256) void attn_kernel(const __half* __restrict__ qkvh,
                                                   __half* __restrict__ out)
{
    gdc_launch();
    gdc_wait();
    int bh = blockIdx.x >> 2, quarter = blockIdx.x & 3;
    int b = bh >> 3, h = bh & 7;
    const int kmax = (quarter + 1) * 20;
    __shared__ __half2 Kt2[80 * 33];   // row stride 33 half2: conflict-free
    __shared__ __half2 Vs2[80 * 32];
    __shared__ float pr[8 * 80];
    const __half* base = qkvh + (size_t)b * SEQ * 3 * EDIM;
    for (int i = threadIdx.x; i < kmax * 32; i += 256) {
        int t = i >> 5, d2 = i & 31;
        Kt2[t * 33 + d2] = *(const __half2*)(base + t * 1536 + 512 + h * 64 + d2 * 2);
        Vs2[t * 32 + d2] = *(const __half2*)(base + t * 1536 + 1024 + h * 64 + d2 * 2);
    }
    __syncthreads();
    int warp = threadIdx.x >> 5, lane = threadIdx.x & 31;
    for (int qi = warp; qi < 20; qi += 8) {
        int q = quarter * 20 + qi;
        const __half2* qrow = (const __half2*)(base + q * 1536 + h * 64);
        int j0 = lane, j1 = lane + 32, j2 = lane + 64;
        const __half2* k0 = &Kt2[j0 * 33];
        const __half2* k1 = &Kt2[(j1 < 80 ? j1 : 0) * 33];
        const __half2* k2 = &Kt2[(j2 < 80 ? j2 : 0) * 33];
        float a0 = 0.f, a1 = 0.f, a2 = 0.f;
#pragma unroll
        for (int kk = 0; kk < 32; kk++) {
            float2 qv = __half22float2(qrow[kk]);     // L1 broadcast
            float2 x0 = __half22float2(k0[kk]);
            float2 x1 = __half22float2(k1[kk]);
            float2 x2 = __half22float2(k2[kk]);
            a0 += qv.x * x0.x + qv.y * x0.y;
            a1 += qv.x * x1.x + qv.y * x1.y;
            a2 += qv.x * x2.x + qv.y * x2.y;
        }
        float s0 = (j0 <= q) ? a0 * 0.125f : -1e30f;
        float s1 = (j1 <= q) ? a1 * 0.125f : -1e30f;
        float s2 = (j2 <= q) ? a2 * 0.125f : -1e30f;
        float m = fmaxf(fmaxf(s0, s1), s2);
#pragma unroll
        for (int o = 16; o; o >>= 1) m = fmaxf(m, __shfl_xor_sync(0xffffffffu, m, o));
        float p0 = (j0 <= q) ? __expf(s0 - m) : 0.f;
        float p1 = (j1 <= q) ? __expf(s1 - m) : 0.f;
        float p2 = (j2 <= q) ? __expf(s2 - m) : 0.f;
        float sum = p0 + p1 + p2;
#pragma unroll
        for (int o = 16; o; o >>= 1) sum += __shfl_xor_sync(0xffffffffu, sum, o);
        float inv = 1.f / sum;
        pr[warp * 80 + j0] = p0 * inv;
        if (j1 < 80) pr[warp * 80 + j1] = p1 * inv;
        if (j2 < 80) pr[warp * 80 + j2] = p2 * inv;
        __syncwarp();
        float o0 = 0.f, o1 = 0.f;   // lane covers dims (2*lane, 2*lane+1)
#pragma unroll 10
        for (int j = 0; j < kmax; j++) {
            float pv = pr[warp * 80 + j];
            float2 vv = __half22float2(Vs2[j * 32 + lane]);
            o0 += pv * vv.x;
            o1 += pv * vv.y;
        }
        *(__half2*)&out[(size_t)(b * 80 + q) * EDIM + h * 64 + 2 * lane] =
            __floats2half2_rn(o0, o1);
        __syncwarp();
    }
}

// ---------------- per-row stats helpers ----------------
__device__ __forceinline__ float2 row_stats(float v0, float v1, float v2, float v3,
                                            float* rs, float* rss, int tid)
{
    float s = v0 + v1 + v2 + v3;
    float ss = v0 * v0 + v1 * v1 + v2 * v2 + v3 * v3;
#pragma unroll
    for (int o = 16; o; o >>= 1) {
        s  += __shfl_xor_sync(0xffffffffu, s, o);
        ss += __shfl_xor_sync(0xffffffffu, ss, o);
    }
    int wid = tid >> 5;
    if ((tid & 31) == 0) { rs[wid] = s; rss[wid] = ss; }
    __syncthreads();
    int base = (tid >> 7) * 4;
    float tots  = rs[base]  + rs[base + 1]  + rs[base + 2]  + rs[base + 3];
    float totss = rss[base] + rss[base + 1] + rss[base + 2] + rss[base + 3];
    float mean = tots * (1.f / 512.f);
    float var = totss * (1.f / 512.f) - mean * mean;
    return make_float2(mean, rsqrtf(var + 1e-5f));
}
__device__ __forceinline__ void st_half4(__half* p, float o0, float o1, float o2, float o3)
{
    __half2 h01 = __floats2half2_rn(o0, o1), h23 = __floats2half2_rn(o2, o3);
    uint2 u;
    u.x = *(uint32_t*)&h01; u.y = *(uint32_t*)&h23;
    *(uint2*)p = u;
}

// ---------------- x = LN(x + a0+a1+a2); PDL ----------------
__global__ __launch_bounds__(256) void add_ln_kernel(
    float* __restrict__ x, __half* __restrict__ xh, const float* __restrict__ add,
    const float* __restrict__ w, const float* __restrict__ b, int writeX)
{
    gdc_launch();
    gdc_wait();
    __shared__ float rs[8], rss[8];
    int tid = threadIdx.x, tt = tid & 127;
    const size_t P = (size_t)NTOK * EDIM;
    size_t off = (size_t)(blockIdx.x * 2 + (tid >> 7)) * EDIM + tt * 4;
    float4 xv = *(const float4*)&x[off];
    float4 a0 = *(const float4*)&add[off];
    float4 a1 = *(const float4*)&add[P + off];
    float4 a2 = *(const float4*)&add[2 * P + off];
    float v0 = xv.x + a0.x + a1.x + a2.x, v1 = xv.y + a0.y + a1.y + a2.y;
    float v2 = xv.z + a0.z + a1.z + a2.z, v3 = xv.w + a0.w + a1.w + a2.w;
    float2 mi = row_stats(v0, v1, v2, v3, rs, rss, tid);
    int c = tt * 4;
    float4 wv = *(const float4*)&w[c], bv = *(const float4*)&b[c];
    float o0 = (v0 - mi.x) * mi.y * wv.x + bv.x;
    float o1 = (v1 - mi.x) * mi.y * wv.y + bv.y;
    float o2 = (v2 - mi.x) * mi.y * wv.z + bv.z;
    float o3 = (v3 - mi.x) * mi.y * wv.w + bv.w;
    if (writeX) *(float4*)&x[off] = make_float4(o0, o1, o2, o3);
    st_half4(&xh[off], o0, o1, o2, o3);
}

// ---------------- fused ln1 + cvec + ln2; PDL ----------------
__global__ __launch_bounds__(256) void add_ln2_kernel(
    float* __restrict__ x, __half* __restrict__ xh, const float* __restrict__ add,
    const float* __restrict__ cv,
    const float* __restrict__ w1, const float* __restrict__ b1,
    const float* __restrict__ w2, const float* __restrict__ b2)
{
    gdc_launch();
    gdc_wait();
    __shared__ float rs[8], rss[8];
    int tid = threadIdx.x, tt = tid & 127;
    const size_t P = (size_t)NTOK * EDIM;
    size_t off = (size_t)(blockIdx.x * 2 + (tid >> 7)) * EDIM + tt * 4;
    float4 xv = *(const float4*)&x[off];
    float4 a0 = *(const float4*)&add[off];
    float4 a1 = *(const float4*)&add[P + off];
    float4 a2 = *(const float4*)&add[2 * P + off];
    float v0 = xv.x + a0.x + a1.x + a2.x, v1 = xv.y + a0.y + a1.y + a2.y;
    float v2 = xv.z + a0.z + a1.z + a2.z, v3 = xv.w + a0.w + a1.w + a2.w;
    float2 mi = row_stats(v0, v1, v2, v3, rs, rss, tid);
    int c = tt * 4;
    float4 wv = *(const float4*)&w1[c], bv = *(const float4*)&b1[c];
    float4 cvv = *(const float4*)&cv[c];
    float y0 = (v0 - mi.x) * mi.y * wv.x + bv.x + cvv.x;
    float y1 = (v1 - mi.x) * mi.y * wv.y + bv.y + cvv.y;
    float y2 = (v2 - mi.x) * mi.y * wv.z + bv.z + cvv.z;
    float y3 = (v3 - mi.x) * mi.y * wv.w + bv.w + cvv.w;
    __syncthreads();
    mi = row_stats(y0, y1, y2, y3, rs, rss, tid);
    wv = *(const float4*)&w2[c]; bv = *(const float4*)&b2[c];
    float o0 = (y0 - mi.x) * mi.y * wv.x + bv.x;
    float o1 = (y1 - mi.x) * mi.y * wv.y + bv.y;
    float o2 = (y2 - mi.x) * mi.y * wv.z + bv.z;
    float o3 = (y3 - mi.x) * mi.y * wv.w + bv.w;
    *(float4*)&x[off] = make_float4(o0, o1, o2, o3);
    st_half4(&xh[off], o0, o1, o2, o3);
}

// ---------------- all-layer cross-attn constant vectors ----------------
__global__ void ca_const_kernel(const float* __restrict__ ow, const float* __restrict__ ib,
                                const float* __restrict__ ob, float* __restrict__ c)
{
    int gw = (blockIdx.x * blockDim.x + threadIdx.x) >> 5;
    int lane = threadIdx.x & 31;
    if (gw >= NLAYER * EDIM) return;
    int layer = gw >> 9, e = gw & 511;
    const float* owl = ow + (size_t)layer * EDIM * EDIM + (size_t)e * EDIM;
    const float* vb = ib + (size_t)layer * 3 * EDIM + 2 * EDIM;
    float s = 0.f;
#pragma unroll
    for (int f = lane; f < EDIM; f += 32) s += owl[f] * vb[f];
#pragma unroll
    for (int o = 16; o; o >>= 1) s += __shfl_xor_sync(0xffffffffu, s, o);
    if (lane == 0) c[gw] = ob[gw] + s;
}

// ---------------- PDL launch helper ----------------
template <typename F, typename... Args>
static void launch_pdl(F kern, dim3 grid, dim3 block, size_t smem, Args... args)
{
    cudaLaunchConfig_t cfg = {};
    cfg.gridDim = grid;
    cfg.blockDim = block;
    cfg.dynamicSmemBytes = smem;
    cfg.stream = 0;
    cudaLaunchAttribute attr[1];
    attr[0].id = cudaLaunchAttributeProgrammaticStreamSerialization;
    attr[0].val.programmaticStreamSerializationAllowed = 1;
    cfg.attrs = attr;
    cfg.numAttrs = 1;
    cudaLaunchKernelEx(&cfg, kern, args...);
}

// ---------------- launch ----------------
extern "C" void kernel_launch(void* const* d_in, const int* in_sizes, int n_in,
                              void* d_out, int out_size)
{
    const int*   caps    = (const int*)  d_in[0];
    const float* W_in    = (const float*)d_in[1];
    const float* b_in    = (const float*)d_in[2];
    const float* pos_emb = (const float*)d_in[3];
    const float* sa_in_w  = (const float*)d_in[4];
    const float* sa_in_b  = (const float*)d_in[5];
    const float* sa_out_w = (const float*)d_in[6];
    const float* sa_out_b = (const float*)d_in[7];
    const float* ca_in_b  = (const float*)d_in[9];
    const float* ca_out_w = (const float*)d_in[10];
    const float* ca_out_b = (const float*)d_in[11];
    const float* ff1_w = (const float*)d_in[12];
    const float* ff1_b = (const float*)d_in[13];
    const float* ff2_w = (const float*)d_in[14];
    const float* ff2_b = (const float*)d_in[15];
    const float* ln1_w = (const float*)d_in[16];
    const float* ln1_b = (const float*)d_in[17];
    const float* ln2_w = (const float*)d_in[18];
    const float* ln2_b = (const float*)d_in[19];
    const float* ln3_w = (const float*)d_in[20];
    const float* ln3_b = (const float*)d_in[21];
    const float* out_w = (const float*)d_in[22];
    const float* out_b = (const float*)d_in[23];

    float *x, *t512, *cvec;
    __half *qkvh, *xh, *t512h, *h1h, *wsain, *wsaout, *wff1, *wff2, *wout;
    cudaGetSymbolAddress((void**)&x, g_x);
    cudaGetSymbolAddress((void**)&t512, g_t512);
    cudaGetSymbolAddress((void**)&cvec, g_c);
    cudaGetSymbolAddress((void**)&qkvh, g_qkvh);
    cudaGetSymbolAddress((void**)&xh, g_xh);
    cudaGetSymbolAddress((void**)&t512h, g_t512h);
    cudaGetSymbolAddress((void**)&h1h, g_h1h);
    cudaGetSymbolAddress((void**)&wsain, g_wsain);
    cudaGetSymbolAddress((void**)&wsaout, g_wsaout);
    cudaGetSymbolAddress((void**)&wff1, g_wff1);
    cudaGetSymbolAddress((void**)&wff2, g_wff2);
    cudaGetSymbolAddress((void**)&wout, g_wout);

    cudaFuncSetAttribute(gemm_k, cudaFuncAttributeMaxDynamicSharedMemorySize, SMEM_G);

    cudaStream_t s2;
    cudaStreamCreateWithFlags(&s2, cudaStreamNonBlocking);
    cudaEvent_t eFork, eSain, eCa, eSaout, eFf1, eFf2, eWout;
    cudaEventCreateWithFlags(&eFork, cudaEventDisableTiming);
    cudaEventCreateWithFlags(&eSain, cudaEventDisableTiming);
    cudaEventCreateWithFlags(&eCa, cudaEventDisableTiming);
    cudaEventCreateWithFlags(&eSaout, cudaEventDisableTiming);
    cudaEventCreateWithFlags(&eFf1, cudaEventDisableTiming);
    cudaEventCreateWithFlags(&eFf2, cudaEventDisableTiming);
    cudaEventCreateWithFlags(&eWout, cudaEventDisableTiming);

    auto convOn = [&](cudaStream_t st, const float* src, __half* dst, size_t nelem) {
        int n4 = (int)(nelem / 4);
        convB_kernel<<<(n4 + 255) / 256, 256, 0, st>>>(src, dst, n4);
    };
    auto gemm = [&](const __half* Aw, const __half* Bw, const float* bias,
                    float* C, __half* Ch, int M, int N, int ldk, int ksp, int K,
                    size_t csplit, int relu) {
        int nz = (K + ksp - 1) / ksp;
        launch_pdl(gemm_k, dim3(M / 128, N / 128, nz), dim3(256), (size_t)SMEM_G,
                   Aw, Bw, bias, C, Ch, M, N, ldk, ksp, K, csplit, relu);
    };

    cudaEventRecord(eFork, 0);
    cudaStreamWaitEvent(s2, eFork, 0);

    embed_kernel<<<NTOK, 256>>>(caps, W_in, b_in, pos_emb, x, xh);
    convOn(s2, sa_in_w, wsain, (size_t)NLAYER * 3 * EDIM * EDIM);
    cudaEventRecord(eSain, s2);
    ca_const_kernel<<<256, 256, 0, s2>>>(ca_out_w, ca_in_b, ca_out_b, cvec);
    cudaEventRecord(eCa, s2);
    convOn(s2, sa_out_w, wsaout, (size_t)NLAYER * EDIM * EDIM);
    cudaEventRecord(eSaout, s2);
    convOn(s2, ff1_w, wff1, (size_t)NLAYER * FFD * EDIM);
    cudaEventRecord(eFf1, s2);

    cudaStreamWaitEvent(0, eSain, 0);
    const size_t CS = (size_t)NTOK * EDIM;
    // qkv: fp16 output only (attn consumes fp16)
    gemm(xh, wsain, sa_in_b, nullptr, qkvh, NTOK, 3 * EDIM, EDIM, EDIM, EDIM, 0, 0);

    convOn(s2, ff2_w, wff2, (size_t)NLAYER * EDIM * FFD);
    cudaEventRecord(eFf2, s2);
    convOn(s2, out_w, wout, (size_t)VOC * EDIM);
    cudaEventRecord(eWout, s2);

    for (int i = 0; i < NLAYER; i++) {
        if (i > 0)
            gemm(xh, wsain + (size_t)i * 3 * EDIM * EDIM, sa_in_b + (size_t)i * 3 * EDIM,
                 nullptr, qkvh, NTOK, 3 * EDIM, EDIM, EDIM, EDIM, 0, 0);
        launch_pdl(attn_kernel, dim3(32 * NHEAD * 4), dim3(256), (size_t)0,
                   (const __half*)qkvh, (__half*)t512h);
        if (i == 0) cudaStreamWaitEvent(0, eSaout, 0);
        gemm(t512h, wsaout + (size_t)i * EDIM * EDIM, sa_out_b + (size_t)i * EDIM,
             t512, nullptr, NTOK, EDIM, EDIM, 192, EDIM, CS, 0);
        if (i == 0) cudaStreamWaitEvent(0, eCa, 0);
        launch_pdl(add_ln2_kernel, dim3(NTOK / 2), dim3(256), (size_t)0,
                   x, xh, (const float*)t512, (const float*)(cvec + i * EDIM),
                   ln1_w + i * EDIM, ln1_b + i * EDIM,
                   ln2_w + i * EDIM, ln2_b + i * EDIM);
        if (i == 0) cudaStreamWaitEvent(0, eFf1, 0);
        gemm(xh, wff1 + (size_t)i * FFD * EDIM, ff1_b + (size_t)i * FFD,
             nullptr, h1h, NTOK, FFD, EDIM, EDIM, EDIM, 0, 1);
        if (i == 0) cudaStreamWaitEvent(0, eFf2, 0);
        gemm(h1h, wff2 + (size_t)i * EDIM * FFD, ff2_b + (size_t)i * EDIM,
             t512, nullptr, NTOK, EDIM, FFD, 704, FFD, CS, 0);
        launch_pdl(add_ln_kernel, dim3(NTOK / 2), dim3(256), (size_t)0,
                   x, xh, (const float*)t512,
                   ln3_w + i * EDIM, ln3_b + i * EDIM, (int)(i < NLAYER - 1));
    }

    cudaStreamWaitEvent(0, eWout, 0);
    gemm(xh, wout, out_b, (float*)d_out, nullptr, NTOK, VOC, EDIM, EDIM, EDIM, 0, 0);
}

// round 15
// speedup vs baseline: 1.2099x; 1.2099x over previous
#include <cuda_runtime.h>
#include <cuda_fp16.h>
#include <cstdint>

#define NTOK 2560
#define EDIM 512
#define NHEAD 8
#define HDIM 64
#define FFD 2048
#define VOC 32000
#define SEQ 80
#define NLAYER 4
#define BK 64

// ---------------- device scratch ----------------
__device__ float g_x[NTOK * EDIM];
__device__ float g_qkv[NTOK * 3 * EDIM];
__device__ float g_c[NLAYER * EDIM];
__device__ __half g_t512p[3 * NTOK * EDIM];   // split-K partials (fp16)
__device__ __half g_xh[NTOK * EDIM];
__device__ __half g_t512h[NTOK * EDIM];
__device__ __half g_h1h[NTOK * FFD];
__device__ __half g_wsain[NLAYER * 3 * EDIM * EDIM];
__device__ __half g_wsaout[NLAYER * EDIM * EDIM];
__device__ __half g_wff1[NLAYER * FFD * EDIM];
__device__ __half g_wff2[NLAYER * EDIM * FFD];
__device__ __half g_wout[(size_t)VOC * EDIM];

// ---------------- PTX helpers ----------------
__device__ __forceinline__ uint32_t smem_u32(const void* p) {
    uint32_t a;
    asm("{ .reg .u64 t; cvta.to.shared.u64 t, %1; cvt.u32.u64 %0, t; }" : "=r"(a) : "l"(p));
    return a;
}
__device__ __forceinline__ void cp16(uint32_t dst, const void* src) {
    asm volatile("cp.async.cg.shared.global [%0], [%1], 16;\n" :: "r"(dst), "l"(src));
}
__device__ __forceinline__ void cp_commit() { asm volatile("cp.async.commit_group;\n" ::: "memory"); }
template <int N>
__device__ __forceinline__ void cp_wait() { asm volatile("cp.async.wait_group %0;\n" :: "n"(N) : "memory"); }

__device__ __forceinline__ void gdc_launch() {
    asm volatile("griddepcontrol.launch_dependents;" ::: "memory");
}
__device__ __forceinline__ void gdc_wait() {
    asm volatile("griddepcontrol.wait;" ::: "memory");
}

__device__ __forceinline__ void ldsm4(uint32_t r[4], uint32_t addr) {
    asm volatile("ldmatrix.sync.aligned.m8n8.x4.shared.b16 {%0,%1,%2,%3},[%4];\n"
                 : "=r"(r[0]), "=r"(r[1]), "=r"(r[2]), "=r"(r[3]) : "r"(addr));
}
__device__ __forceinline__ void mma16816(float d[4], const uint32_t a[4], const uint32_t b[2]) {
    asm volatile(
        "mma.sync.aligned.m16n8k16.row.col.f32.f16.f16.f32 "
        "{%0,%1,%2,%3},{%4,%5,%6,%7},{%8,%9},{%0,%1,%2,%3};\n"
        : "+f"(d[0]), "+f"(d[1]), "+f"(d[2]), "+f"(d[3])
        : "r"(a[0]), "r"(a[1]), "r"(a[2]), "r"(a[3]), "r"(b[0]), "r"(b[1]));
}
__device__ __forceinline__ uint32_t swz(uint32_t off) { return off ^ ((off >> 3) & 0x70); }

// ---------------- pipelined fp16 HMMA GEMM, 128x128 CTA, split-K, PDL ----
// Outputs: C (fp32 final, nz==1 only), Ch (fp16 final), Cp (fp16 split-K partials)
#define BMt 128
#define BNt 128
#define NTN 8
#define NSTG 3
#define STB ((BMt + BNt) * 128)
#define SMEM_G (NSTG * STB)

__global__ void __launch_bounds__(256, 2) gemm_k(
    const __half* __restrict__ A, const __half* __restrict__ B,
    const float* __restrict__ bias, float* __restrict__ C, __half* __restrict__ Ch,
    __half* __restrict__ Cp,
    int M, int N, int ldk, int ksp, int K, size_t csplit, int dorelu)
{
    extern __shared__ __align__(16) char sm[];
    const int tid = threadIdx.x, lane = tid & 31, warp = tid >> 5;
    const int bm = blockIdx.x * BMt, bn = blockIdx.y * BNt;
    const int z = blockIdx.z;
    const int k0 = z * ksp;
    const int klen = min(ksp, K - k0);
    const int S = klen / BK;
    const int wm = (warp & 3) * 32, wn = (warp >> 2) * (NTN * 8);
    const uint32_t smem0 = smem_u32(sm);

    float acc[2][NTN][4] = {};

    gdc_launch();

    // prologue part 1: B (weight) tiles — independent of predecessor output
#pragma unroll
    for (int s = 0; s < NSTG - 1; s++) {
        if (s < S) {
            uint32_t b0 = smem0 + (uint32_t)s * STB + (uint32_t)BMt * 128;
            int kabs = k0 + s * BK;
#pragma unroll
            for (int i = tid; i < BNt * 8; i += 256) {
                int r = i >> 3, cb = (i & 7) * 16;
                cp16(b0 + swz(r * 128 + cb),
                     (const char*)(B + (size_t)(bn + r) * ldk + kabs) + cb);
            }
        }
    }

    gdc_wait();

    // prologue part 2: A tiles + per-stage commits
#pragma unroll
    for (int s = 0; s < NSTG - 1; s++) {
        if (s < S) {
            uint32_t a0 = smem0 + (uint32_t)s * STB;
            int kabs = k0 + s * BK;
#pragma unroll
            for (int i = tid; i < BMt * 8; i += 256) {
                int r = i >> 3, cb = (i & 7) * 16;
                cp16(a0 + swz(r * 128 + cb),
                     (const char*)(A + (size_t)(bm + r) * ldk + kabs) + cb);
            }
        }
        cp_commit();
    }

    auto load_stage = [&](int st, int kabs) {
        uint32_t b0 = smem0 + (uint32_t)st * STB;
#pragma unroll
        for (int i = tid; i < (BMt + BNt) * 8; i += 256) {
            int r = i >> 3, cb = (i & 7) * 16;
            bool isA = r < BMt;
            int rr = isA ? r : r - BMt;
            uint32_t dst = b0 + (isA ? 0u : (uint32_t)BMt * 128) + swz(rr * 128 + cb);
            const char* p = isA ? (const char*)(A + (size_t)(bm + rr) * ldk + kabs) + cb
                                : (const char*)(B + (size_t)(bn + rr) * ldk + kabs) + cb;
            cp16(dst, p);
        }
    };

    const int lrow = lane & 7, seg = lane >> 3;
    for (int s = 0; s < S; s++) {
        cp_wait<NSTG - 2>();
        __syncthreads();
        if (s + NSTG - 1 < S) load_stage((s + NSTG - 1) % NSTG, k0 + (s + NSTG - 1) * BK);
        cp_commit();

        uint32_t b0 = smem0 + (uint32_t)(s % NSTG) * STB;
        uint32_t aA = b0, bB = b0 + (uint32_t)BMt * 128;

        uint32_t af[2][2][4];
#pragma unroll
        for (int mt = 0; mt < 2; mt++)
            ldsm4(af[0][mt], aA + swz((wm + mt * 16 + (lane & 15)) * 128 + (lane >> 4) * 16));

#pragma unroll
        for (int kc = 0; kc < 4; kc++) {
            const int kb = kc * 32;
            const int cur = kc & 1, nxt = cur ^ 1;
            uint32_t bfr[NTN][2];
#pragma unroll
            for (int nt = 0; nt < NTN; nt += 2) {
                uint32_t t4[4];
                ldsm4(t4, bB + swz((wn + (nt + (seg >> 1)) * 8 + lrow) * 128 +
                                   kb + (seg & 1) * 16));
                bfr[nt][0] = t4[0]; bfr[nt][1] = t4[1];
                bfr[nt + 1][0] = t4[2]; bfr[nt + 1][1] = t4[3];
            }
            if (kc < 3) {
                const int kb2 = kb + 32;
#pragma unroll
                for (int mt = 0; mt < 2; mt++)
                    ldsm4(af[nxt][mt], aA + swz((wm + mt * 16 + (lane & 15)) * 128 +
                                                kb2 + (lane >> 4) * 16));
            }
#pragma unroll
            for (int mt = 0; mt < 2; mt++)
#pragma unroll
                for (int nt = 0; nt < NTN; nt++)
                    mma16816(acc[mt][nt], af[cur][mt], bfr[nt]);
        }
    }

    __half* Pz = Cp ? Cp + (size_t)z * csplit : nullptr;
#pragma unroll
    for (int mt = 0; mt < 2; mt++) {
#pragma unroll
        for (int nt = 0; nt < NTN; nt++) {
            int row = bm + wm + mt * 16 + (lane >> 2);
            int col = bn + wn + nt * 8 + (lane & 3) * 2;
            float b0 = (z == 0) ? bias[col] : 0.f;
            float b1 = (z == 0) ? bias[col + 1] : 0.f;
            float v0 = acc[mt][nt][0] + b0, v1 = acc[mt][nt][1] + b1;
            float v2 = acc[mt][nt][2] + b0, v3 = acc[mt][nt][3] + b1;
            if (dorelu) {
                v0 = fmaxf(v0, 0.f); v1 = fmaxf(v1, 0.f);
                v2 = fmaxf(v2, 0.f); v3 = fmaxf(v3, 0.f);
            }
            if (C) {
                *(float2*)&C[(size_t)row * N + col] = make_float2(v0, v1);
                *(float2*)&C[(size_t)(row + 8) * N + col] = make_float2(v2, v3);
            }
            if (Pz) {
                *(__half2*)&Pz[(size_t)row * N + col] = __floats2half2_rn(v0, v1);
                *(__half2*)&Pz[(size_t)(row + 8) * N + col] = __floats2half2_rn(v2, v3);
            }
            if (Ch) {
                *(__half2*)&Ch[(size_t)row * N + col] = __floats2half2_rn(v0, v1);
                *(__half2*)&Ch[(size_t)(row + 8) * N + col] = __floats2half2_rn(v2, v3);
            }
        }
    }
}

// ---------------- fp32 -> fp16 weights ----------------
__global__ void convB_kernel(const float* __restrict__ s, __half* __restrict__ o, int n4)
{
    int i = blockIdx.x * blockDim.x + threadIdx.x;
    if (i >= n4) return;
    float4 v = ((const float4*)s)[i];
    ((__half2*)o)[2 * i]     = __floats2half2_rn(v.x, v.y);
    ((__half2*)o)[2 * i + 1] = __floats2half2_rn(v.z, v.w);
}

// ---------------- embedding gather ----------------
__global__ __launch_bounds__(256) void embed_kernel(
    const int* __restrict__ caps, const float* __restrict__ Win,
    const float* __restrict__ bin, const float* __restrict__ pos,
    float* __restrict__ x, __half* __restrict__ xh)
{
    int n = blockIdx.x;
    int tok = caps[n];
    int l = n % SEQ;
#pragma unroll
    for (int e = threadIdx.x; e < EDIM; e += 256) {
        float v = Win[(size_t)e * VOC + tok] + bin[e] + pos[l * EDIM + e];
        x[(size_t)n * EDIM + e] = v;
        xh[(size_t)n * EDIM + e] = __float2half_rn(v);
    }
}

// ---------------- causal self-attention: 4 q-quarters per (b,h), fp32, PDL --------
__global__ __launch_bounds__(256) void attn_kernel(const float* __restrict__ qkv,
                                                   __half* __restrict__ out)
{
    gdc_launch();
    gdc_wait();
    int bh = blockIdx.x >> 2, quarter = blockIdx.x & 3;
    int b = bh >> 3, h = bh & 7;
    const int kmax = (quarter + 1) * 20;
    __shared__ float Kt[80 * 65];
    __shared__ float Vs[80 * 64];
    __shared__ float pr[8 * 80];
    const float* base = qkv + (size_t)b * SEQ * 3 * EDIM;
    for (int i = threadIdx.x; i < kmax * 64; i += 256) {
        int t = i >> 6, d = i & 63;
        Kt[t * 65 + d] = base[t * 1536 + 512 + h * 64 + d];
        Vs[i]          = base[t * 1536 + 1024 + h * 64 + d];
    }
    __syncthreads();
    int warp = threadIdx.x >> 5, lane = threadIdx.x & 31;
    for (int qi = warp; qi < 20; qi += 8) {
        int q = quarter * 20 + qi;
        const float4* qrow = (const float4*)(base + q * 1536 + h * 64);
        int j0 = lane, j1 = lane + 32, j2 = lane + 64;
        const float* k0 = &Kt[j0 * 65];
        const float* k1 = &Kt[(j1 < 80 ? j1 : 0) * 65];
        const float* k2 = &Kt[(j2 < 80 ? j2 : 0) * 65];
        float a0 = 0.f, a1 = 0.f, a2 = 0.f;
#pragma unroll
        for (int kk = 0; kk < 16; kk++) {
            float4 qv = qrow[kk];
            int kb = kk * 4;
            a0 += qv.x * k0[kb] + qv.y * k0[kb + 1] + qv.z * k0[kb + 2] + qv.w * k0[kb + 3];
            a1 += qv.x * k1[kb] + qv.y * k1[kb + 1] + qv.z * k1[kb + 2] + qv.w * k1[kb + 3];
            a2 += qv.x * k2[kb] + qv.y * k2[kb + 1] + qv.z * k2[kb + 2] + qv.w * k2[kb + 3];
        }
        float s0 = (j0 <= q) ? a0 * 0.125f : -1e30f;
        float s1 = (j1 <= q) ? a1 * 0.125f : -1e30f;
        float s2 = (j2 <= q) ? a2 * 0.125f : -1e30f;
        float m = fmaxf(fmaxf(s0, s1), s2);
#pragma unroll
        for (int o = 16; o; o >>= 1) m = fmaxf(m, __shfl_xor_sync(0xffffffffu, m, o));
        float p0 = (j0 <= q) ? __expf(s0 - m) : 0.f;
        float p1 = (j1 <= q) ? __expf(s1 - m) : 0.f;
        float p2 = (j2 <= q) ? __expf(s2 - m) : 0.f;
        float sum = p0 + p1 + p2;
#pragma unroll
        for (int o = 16; o; o >>= 1) sum += __shfl_xor_sync(0xffffffffu, sum, o);
        float inv = 1.f / sum;
        pr[warp * 80 + j0] = p0 * inv;
        if (j1 < 80) pr[warp * 80 + j1] = p1 * inv;
        if (j2 < 80) pr[warp * 80 + j2] = p2 * inv;
        __syncwarp();
        float o0 = 0.f, o1 = 0.f;
#pragma unroll 10
        for (int j = 0; j < kmax; j++) {
            float pv = pr[warp * 80 + j];
            o0 += pv * Vs[j * 64 + lane];
            o1 += pv * Vs[j * 64 + 32 + lane];
        }
        out[(size_t)(b * 80 + q) * EDIM + h * 64 + lane] = __float2half_rn(o0);
        out[(size_t)(b * 80 + q) * EDIM + h * 64 + 32 + lane] = __float2half_rn(o1);
        __syncwarp();
    }
}

// ---------------- per-row stats helpers ----------------
__device__ __forceinline__ float2 row_stats(float v0, float v1, float v2, float v3,
                                            float* rs, float* rss, int tid)
{
    float s = v0 + v1 + v2 + v3;
    float ss = v0 * v0 + v1 * v1 + v2 * v2 + v3 * v3;
#pragma unroll
    for (int o = 16; o; o >>= 1) {
        s  += __shfl_xor_sync(0xffffffffu, s, o);
        ss += __shfl_xor_sync(0xffffffffu, ss, o);
    }
    int wid = tid >> 5;
    if ((tid & 31) == 0) { rs[wid] = s; rss[wid] = ss; }
    __syncthreads();
    int base = (tid >> 7) * 4;
    float tots  = rs[base]  + rs[base + 1]  + rs[base + 2]  + rs[base + 3];
    float totss = rss[base] + rss[base + 1] + rss[base + 2] + rss[base + 3];
    float mean = tots * (1.f / 512.f);
    float var = totss * (1.f / 512.f) - mean * mean;
    return make_float2(mean, rsqrtf(var + 1e-5f));
}
__device__ __forceinline__ void st_half4(__half* p, float o0, float o1, float o2, float o3)
{
    __half2 h01 = __floats2half2_rn(o0, o1), h23 = __floats2half2_rn(o2, o3);
    uint2 u;
    u.x = *(uint32_t*)&h01; u.y = *(uint32_t*)&h23;
    *(uint2*)p = u;
}
// load 4 halves at p, return as 4 floats
__device__ __forceinline__ float4 ld_half4(const __half* p)
{
    uint2 u = *(const uint2*)p;
    __half2 h01 = *(__half2*)&u.x, h23 = *(__half2*)&u.y;
    float2 f01 = __half22float2(h01), f23 = __half22float2(h23);
    return make_float4(f01.x, f01.y, f23.x, f23.y);
}

// ---------------- x = LN(x + p0+p1+p2); partials fp16; PDL ----------------
__global__ __launch_bounds__(256) void add_ln_kernel(
    float* __restrict__ x, __half* __restrict__ xh, const __half* __restrict__ add,
    const float* __restrict__ w, const float* __restrict__ b, int writeX)
{
    gdc_launch();
    gdc_wait();
    __shared__ float rs[8], rss[8];
    int tid = threadIdx.x, tt = tid & 127;
    const size_t P = (size_t)NTOK * EDIM;
    size_t off = (size_t)(blockIdx.x * 2 + (tid >> 7)) * EDIM + tt * 4;
    float4 xv = *(const float4*)&x[off];
    float4 a0 = ld_half4(add + off);
    float4 a1 = ld_half4(add + P + off);
    float4 a2 = ld_half4(add + 2 * P + off);
    float v0 = xv.x + a0.x + a1.x + a2.x, v1 = xv.y + a0.y + a1.y + a2.y;
    float v2 = xv.z + a0.z + a1.z + a2.z, v3 = xv.w + a0.w + a1.w + a2.w;
    float2 mi = row_stats(v0, v1, v2, v3, rs, rss, tid);
    int c = tt * 4;
    float4 wv = *(const float4*)&w[c], bv = *(const float4*)&b[c];
    float o0 = (v0 - mi.x) * mi.y * wv.x + bv.x;
    float o1 = (v1 - mi.x) * mi.y * wv.y + bv.y;
    float o2 = (v2 - mi.x) * mi.y * wv.z + bv.z;
    float o3 = (v3 - mi.x) * mi.y * wv.w + bv.w;
    if (writeX) *(float4*)&x[off] = make_float4(o0, o1, o2, o3);
    st_half4(&xh[off], o0, o1, o2, o3);
}

// ---------------- fused ln1 + cvec + ln2; partials fp16; PDL ----------------
__global__ __launch_bounds__(256) void add_ln2_kernel(
    float* __restrict__ x, __half* __restrict__ xh, const __half* __restrict__ add,
    const float* __restrict__ cv,
    const float* __restrict__ w1, const float* __restrict__ b1,
    const float* __restrict__ w2, const float* __restrict__ b2)
{
    gdc_launch();
    gdc_wait();
    __shared__ float rs[8], rss[8];
    int tid = threadIdx.x, tt = tid & 127;
    const size_t P = (size_t)NTOK * EDIM;
    size_t off = (size_t)(blockIdx.x * 2 + (tid >> 7)) * EDIM + tt * 4;
    float4 xv = *(const float4*)&x[off];
    float4 a0 = ld_half4(add + off);
    float4 a1 = ld_half4(add + P + off);
    float4 a2 = ld_half4(add + 2 * P + off);
    float v0 = xv.x + a0.x + a1.x + a2.x, v1 = xv.y + a0.y + a1.y + a2.y;
    float v2 = xv.z + a0.z + a1.z + a2.z, v3 = xv.w + a0.w + a1.w + a2.w;
    float2 mi = row_stats(v0, v1, v2, v3, rs, rss, tid);
    int c = tt * 4;
    float4 wv = *(const float4*)&w1[c], bv = *(const float4*)&b1[c];
    float4 cvv = *(const float4*)&cv[c];
    float y0 = (v0 - mi.x) * mi.y * wv.x + bv.x + cvv.x;
    float y1 = (v1 - mi.x) * mi.y * wv.y + bv.y + cvv.y;
    float y2 = (v2 - mi.x) * mi.y * wv.z + bv.z + cvv.z;
    float y3 = (v3 - mi.x) * mi.y * wv.w + bv.w + cvv.w;
    __syncthreads();
    mi = row_stats(y0, y1, y2, y3, rs, rss, tid);
    wv = *(const float4*)&w2[c]; bv = *(const float4*)&b2[c];
    float o0 = (y0 - mi.x) * mi.y * wv.x + bv.x;
    float o1 = (y1 - mi.x) * mi.y * wv.y + bv.y;
    float o2 = (y2 - mi.x) * mi.y * wv.z + bv.z;
    float o3 = (y3 - mi.x) * mi.y * wv.w + bv.w;
    *(float4*)&x[off] = make_float4(o0, o1, o2, o3);
    st_half4(&xh[off], o0, o1, o2, o3);
}

// ---------------- all-layer cross-attn constant vectors ----------------
__global__ void ca_const_kernel(const float* __restrict__ ow, const float* __restrict__ ib,
                                const float* __restrict__ ob, float* __restrict__ c)
{
    int gw = (blockIdx.x * blockDim.x + threadIdx.x) >> 5;
    int lane = threadIdx.x & 31;
    if (gw >= NLAYER * EDIM) return;
    int layer = gw >> 9, e = gw & 511;
    const float* owl = ow + (size_t)layer * EDIM * EDIM + (size_t)e * EDIM;
    const float* vb = ib + (size_t)layer * 3 * EDIM + 2 * EDIM;
    float s = 0.f;
#pragma unroll
    for (int f = lane; f < EDIM; f += 32) s += owl[f] * vb[f];
#pragma unroll
    for (int o = 16; o; o >>= 1) s += __shfl_xor_sync(0xffffffffu, s, o);
    if (lane == 0) c[gw] = ob[gw] + s;
}

// ---------------- PDL launch helper ----------------
template <typename F, typename... Args>
static void launch_pdl(F kern, dim3 grid, dim3 block, size_t smem, Args... args)
{
    cudaLaunchConfig_t cfg = {};
    cfg.gridDim = grid;
    cfg.blockDim = block;
    cfg.dynamicSmemBytes = smem;
    cfg.stream = 0;
    cudaLaunchAttribute attr[1];
    attr[0].id = cudaLaunchAttributeProgrammaticStreamSerialization;
    attr[0].val.programmaticStreamSerializationAllowed = 1;
    cfg.attrs = attr;
    cfg.numAttrs = 1;
    cudaLaunchKernelEx(&cfg, kern, args...);
}

// ---------------- launch ----------------
extern "C" void kernel_launch(void* const* d_in, const int* in_sizes, int n_in,
                              void* d_out, int out_size)
{
    const int*   caps    = (const int*)  d_in[0];
    const float* W_in    = (const float*)d_in[1];
    const float* b_in    = (const float*)d_in[2];
    const float* pos_emb = (const float*)d_in[3];
    const float* sa_in_w  = (const float*)d_in[4];
    const float* sa_in_b  = (const float*)d_in[5];
    const float* sa_out_w = (const float*)d_in[6];
    const float* sa_out_b = (const float*)d_in[7];
    const float* ca_in_b  = (const float*)d_in[9];
    const float* ca_out_w = (const float*)d_in[10];
    const float* ca_out_b = (const float*)d_in[11];
    const float* ff1_w = (const float*)d_in[12];
    const float* ff1_b = (const float*)d_in[13];
    const float* ff2_w = (const float*)d_in[14];
    const float* ff2_b = (const float*)d_in[15];
    const float* ln1_w = (const float*)d_in[16];
    const float* ln1_b = (const float*)d_in[17];
    const float* ln2_w = (const float*)d_in[18];
    const float* ln2_b = (const float*)d_in[19];
    const float* ln3_w = (const float*)d_in[20];
    const float* ln3_b = (const float*)d_in[21];
    const float* out_w = (const float*)d_in[22];
    const float* out_b = (const float*)d_in[23];

    float *x, *qkv, *cvec;
    __half *t512p, *xh, *t512h, *h1h, *wsain, *wsaout, *wff1, *wff2, *wout;
    cudaGetSymbolAddress((void**)&x, g_x);
    cudaGetSymbolAddress((void**)&qkv, g_qkv);
    cudaGetSymbolAddress((void**)&cvec, g_c);
    cudaGetSymbolAddress((void**)&t512p, g_t512p);
    cudaGetSymbolAddress((void**)&xh, g_xh);
    cudaGetSymbolAddress((void**)&t512h, g_t512h);
    cudaGetSymbolAddress((void**)&h1h, g_h1h);
    cudaGetSymbolAddress((void**)&wsain, g_wsain);
    cudaGetSymbolAddress((void**)&wsaout, g_wsaout);
    cudaGetSymbolAddress((void**)&wff1, g_wff1);
    cudaGetSymbolAddress((void**)&wff2, g_wff2);
    cudaGetSymbolAddress((void**)&wout, g_wout);

    cudaFuncSetAttribute(gemm_k, cudaFuncAttributeMaxDynamicSharedMemorySize, SMEM_G);

    cudaStream_t s2;
    cudaStreamCreateWithFlags(&s2, cudaStreamNonBlocking);
    cudaEvent_t eFork, eSain, eCa, eSaout, eFf1, eFf2, eWout;
    cudaEventCreateWithFlags(&eFork, cudaEventDisableTiming);
    cudaEventCreateWithFlags(&eSain, cudaEventDisableTiming);
    cudaEventCreateWithFlags(&eCa, cudaEventDisableTiming);
    cudaEventCreateWithFlags(&eSaout, cudaEventDisableTiming);
    cudaEventCreateWithFlags(&eFf1, cudaEventDisableTiming);
    cudaEventCreateWithFlags(&eFf2, cudaEventDisableTiming);
    cudaEventCreateWithFlags(&eWout, cudaEventDisableTiming);

    auto convOn = [&](cudaStream_t st, const float* src, __half* dst, size_t nelem) {
        int n4 = (int)(nelem / 4);
        convB_kernel<<<(n4 + 255) / 256, 256, 0, st>>>(src, dst, n4);
    };
    auto gemm = [&](const __half* Aw, const __half* Bw, const float* bias,
                    float* C, __half* Ch, __half* Cp, int M, int N, int ldk, int ksp,
                    int K, size_t csplit, int relu) {
        int nz = (K + ksp - 1) / ksp;
        launch_pdl(gemm_k, dim3(M / 128, N / 128, nz), dim3(256), (size_t)SMEM_G,
                   Aw, Bw, bias, C, Ch, Cp, M, N, ldk, ksp, K, csplit, relu);
    };

    cudaEventRecord(eFork, 0);
    cudaStreamWaitEvent(s2, eFork, 0);

    embed_kernel<<<NTOK, 256>>>(caps, W_in, b_in, pos_emb, x, xh);
    convOn(s2, sa_in_w, wsain, (size_t)NLAYER * 3 * EDIM * EDIM);
    cudaEventRecord(eSain, s2);
    ca_const_kernel<<<256, 256, 0, s2>>>(ca_out_w, ca_in_b, ca_out_b, cvec);
    cudaEventRecord(eCa, s2);
    convOn(s2, sa_out_w, wsaout, (size_t)NLAYER * EDIM * EDIM);
    cudaEventRecord(eSaout, s2);
    convOn(s2, ff1_w, wff1, (size_t)NLAYER * FFD * EDIM);
    cudaEventRecord(eFf1, s2);

    cudaStreamWaitEvent(0, eSain, 0);
    const size_t CS = (size_t)NTOK * EDIM;
    gemm(xh, wsain, sa_in_b, qkv, nullptr, nullptr, NTOK, 3 * EDIM, EDIM, EDIM, EDIM, 0, 0);

    convOn(s2, ff2_w, wff2, (size_t)NLAYER * EDIM * FFD);
    cudaEventRecord(eFf2, s2);
    convOn(s2, out_w, wout, (size_t)VOC * EDIM);
    cudaEventRecord(eWout, s2);

    for (int i = 0; i < NLAYER; i++) {
        if (i > 0)
            gemm(xh, wsain + (size_t)i * 3 * EDIM * EDIM, sa_in_b + (size_t)i * 3 * EDIM,
                 qkv, nullptr, nullptr, NTOK, 3 * EDIM, EDIM, EDIM, EDIM, 0, 0);
        launch_pdl(attn_kernel, dim3(32 * NHEAD * 4), dim3(256), (size_t)0,
                   (const float*)qkv, (__half*)t512h);
        if (i == 0) cudaStreamWaitEvent(0, eSaout, 0);
        gemm(t512h, wsaout + (size_t)i * EDIM * EDIM, sa_out_b + (size_t)i * EDIM,
             nullptr, nullptr, t512p, NTOK, EDIM, EDIM, 192, EDIM, CS, 0);
        if (i == 0) cudaStreamWaitEvent(0, eCa, 0);
        launch_pdl(add_ln2_kernel, dim3(NTOK / 2), dim3(256), (size_t)0,
                   x, xh, (const __half*)t512p, (const float*)(cvec + i * EDIM),
                   ln1_w + i * EDIM, ln1_b + i * EDIM,
                   ln2_w + i * EDIM, ln2_b + i * EDIM);
        if (i == 0) cudaStreamWaitEvent(0, eFf1, 0);
        gemm(xh, wff1 + (size_t)i * FFD * EDIM, ff1_b + (size_t)i * FFD,
             nullptr, h1h, nullptr, NTOK, FFD, EDIM, EDIM, EDIM, 0, 1);
        if (i == 0) cudaStreamWaitEvent(0, eFf2, 0);
        gemm(h1h, wff2 + (size_t)i * EDIM * FFD, ff2_b + (size_t)i * EDIM,
             nullptr, nullptr, t512p, NTOK, EDIM, FFD, 704, FFD, CS, 0);
        launch_pdl(add_ln_kernel, dim3(NTOK / 2), dim3(256), (size_t)0,
                   x, xh, (const __half*)t512p,
                   ln3_w + i * EDIM, ln3_b + i * EDIM, (int)(i < NLAYER - 1));
    }

    cudaStreamWaitEvent(0, eWout, 0);
    gemm(xh, wout, out_b, (float*)d_out, nullptr, nullptr, NTOK, VOC, EDIM, EDIM, EDIM, 0, 0);
}

// round 16
// speedup vs baseline: 1.2511x; 1.0341x over previous
#include <cuda_runtime.h>
#include <cuda_fp16.h>
#include <cstdint>

#define NTOK 2560
#define EDIM 512
#define NHEAD 8
#define HDIM 64
#define FFD 2048
#define VOC 32000
#define SEQ 80
#define NLAYER 4
#define BK 64

// ---------------- device scratch ----------------
__device__ float g_x[NTOK * EDIM];
__device__ float g_qkv[NTOK * 3 * EDIM];
__device__ float g_t512[3 * NTOK * EDIM];
__device__ float g_c[NLAYER * EDIM];
__device__ __half g_xh[NTOK * EDIM];
__device__ __half g_t512h[NTOK * EDIM];
__device__ __half g_h1h[NTOK * FFD];
__device__ __half g_wsain[NLAYER * 3 * EDIM * EDIM];
__device__ __half g_wsaout[NLAYER * EDIM * EDIM];
__device__ __half g_wff1[NLAYER * FFD * EDIM];
__device__ __half g_wff2[NLAYER * EDIM * FFD];
__device__ __half g_wout[(size_t)VOC * EDIM];

// ---------------- PTX helpers ----------------
__device__ __forceinline__ uint32_t smem_u32(const void* p) {
    uint32_t a;
    asm("{ .reg .u64 t; cvta.to.shared.u64 t, %1; cvt.u32.u64 %0, t; }" : "=r"(a) : "l"(p));
    return a;
}
__device__ __forceinline__ void cp16(uint32_t dst, const void* src) {
    asm volatile("cp.async.cg.shared.global [%0], [%1], 16;\n" :: "r"(dst), "l"(src));
}
__device__ __forceinline__ void cp_commit() { asm volatile("cp.async.commit_group;\n" ::: "memory"); }
template <int N>
__device__ __forceinline__ void cp_wait() { asm volatile("cp.async.wait_group %0;\n" :: "n"(N) : "memory"); }

__device__ __forceinline__ void gdc_launch() {
    asm volatile("griddepcontrol.launch_dependents;" ::: "memory");
}
__device__ __forceinline__ void gdc_wait() {
    asm volatile("griddepcontrol.wait;" ::: "memory");
}

__device__ __forceinline__ void ldsm4(uint32_t r[4], uint32_t addr) {
    asm volatile("ldmatrix.sync.aligned.m8n8.x4.shared.b16 {%0,%1,%2,%3},[%4];\n"
                 : "=r"(r[0]), "=r"(r[1]), "=r"(r[2]), "=r"(r[3]) : "r"(addr));
}
__device__ __forceinline__ void mma16816(float d[4], const uint32_t a[4], const uint32_t b[2]) {
    asm volatile(
        "mma.sync.aligned.m16n8k16.row.col.f32.f16.f16.f32 "
        "{%0,%1,%2,%3},{%4,%5,%6,%7},{%8,%9},{%0,%1,%2,%3};\n"
        : "+f"(d[0]), "+f"(d[1]), "+f"(d[2]), "+f"(d[3])
        : "r"(a[0]), "r"(a[1]), "r"(a[2]), "r"(a[3]), "r"(b[0]), "r"(b[1]));
}
__device__ __forceinline__ uint32_t swz(uint32_t off) { return off ^ ((off >> 3) & 0x70); }

// ---------------- pipelined fp16 HMMA GEMM, 128x128 CTA, split-K, PDL ----
#define BMt 128
#define BNt 128
#define NTN 8
#define NSTG 3
#define STB ((BMt + BNt) * 128)
#define SMEM_G (NSTG * STB)

__global__ void __launch_bounds__(256, 2) gemm_k(
    const __half* __restrict__ A, const __half* __restrict__ B,
    const float* __restrict__ bias, float* __restrict__ C, __half* __restrict__ Ch,
    int M, int N, int ldk, int ksp, int K, size_t csplit, int dorelu)
{
    extern __shared__ __align__(16) char sm[];
    const int tid = threadIdx.x, lane = tid & 31, warp = tid >> 5;
    const int bm = blockIdx.x * BMt, bn = blockIdx.y * BNt;
    const int z = blockIdx.z;
    const int k0 = z * ksp;
    const int klen = min(ksp, K - k0);
    const int S = klen / BK;
    const int wm = (warp & 3) * 32, wn = (warp >> 2) * (NTN * 8);
    const uint32_t smem0 = smem_u32(sm);

    float acc[2][NTN][4] = {};

    gdc_launch();

    // prologue part 1: B (weight) tiles — independent of predecessor output
#pragma unroll
    for (int s = 0; s < NSTG - 1; s++) {
        if (s < S) {
            uint32_t b0 = smem0 + (uint32_t)s * STB + (uint32_t)BMt * 128;
            int kabs = k0 + s * BK;
#pragma unroll
            for (int i = tid; i < BNt * 8; i += 256) {
                int r = i >> 3, cb = (i & 7) * 16;
                cp16(b0 + swz(r * 128 + cb),
                     (const char*)(B + (size_t)(bn + r) * ldk + kabs) + cb);
            }
        }
    }

    gdc_wait();

    // prologue part 2: A tiles + per-stage commits
#pragma unroll
    for (int s = 0; s < NSTG - 1; s++) {
        if (s < S) {
            uint32_t a0 = smem0 + (uint32_t)s * STB;
            int kabs = k0 + s * BK;
#pragma unroll
            for (int i = tid; i < BMt * 8; i += 256) {
                int r = i >> 3, cb = (i & 7) * 16;
                cp16(a0 + swz(r * 128 + cb),
                     (const char*)(A + (size_t)(bm + r) * ldk + kabs) + cb);
            }
        }
        cp_commit();
    }

    auto load_stage = [&](int st, int kabs) {
        uint32_t b0 = smem0 + (uint32_t)st * STB;
#pragma unroll
        for (int i = tid; i < (BMt + BNt) * 8; i += 256) {
            int r = i >> 3, cb = (i & 7) * 16;
            bool isA = r < BMt;
            int rr = isA ? r : r - BMt;
            uint32_t dst = b0 + (isA ? 0u : (uint32_t)BMt * 128) + swz(rr * 128 + cb);
            const char* p = isA ? (const char*)(A + (size_t)(bm + rr) * ldk + kabs) + cb
                                : (const char*)(B + (size_t)(bn + rr) * ldk + kabs) + cb;
            cp16(dst, p);
        }
    };

    const int lrow = lane & 7, seg = lane >> 3;
    for (int s = 0; s < S; s++) {
        cp_wait<NSTG - 2>();
        __syncthreads();
        if (s + NSTG - 1 < S) load_stage((s + NSTG - 1) % NSTG, k0 + (s + NSTG - 1) * BK);
        cp_commit();

        uint32_t b0 = smem0 + (uint32_t)(s % NSTG) * STB;
        uint32_t aA = b0, bB = b0 + (uint32_t)BMt * 128;

        uint32_t af[2][2][4];
#pragma unroll
        for (int mt = 0; mt < 2; mt++)
            ldsm4(af[0][mt], aA + swz((wm + mt * 16 + (lane & 15)) * 128 + (lane >> 4) * 16));

#pragma unroll
        for (int kc = 0; kc < 4; kc++) {
            const int kb = kc * 32;
            const int cur = kc & 1, nxt = cur ^ 1;
            uint32_t bfr[NTN][2];
#pragma unroll
            for (int nt = 0; nt < NTN; nt += 2) {
                uint32_t t4[4];
                ldsm4(t4, bB + swz((wn + (nt + (seg >> 1)) * 8 + lrow) * 128 +
                                   kb + (seg & 1) * 16));
                bfr[nt][0] = t4[0]; bfr[nt][1] = t4[1];
                bfr[nt + 1][0] = t4[2]; bfr[nt + 1][1] = t4[3];
            }
            if (kc < 3) {
                const int kb2 = kb + 32;
#pragma unroll
                for (int mt = 0; mt < 2; mt++)
                    ldsm4(af[nxt][mt], aA + swz((wm + mt * 16 + (lane & 15)) * 128 +
                                                kb2 + (lane >> 4) * 16));
            }
#pragma unroll
            for (int mt = 0; mt < 2; mt++)
#pragma unroll
                for (int nt = 0; nt < NTN; nt++)
                    mma16816(acc[mt][nt], af[cur][mt], bfr[nt]);
        }
    }

    float* Cz = C ? C + (size_t)z * csplit : nullptr;
#pragma unroll
    for (int mt = 0; mt < 2; mt++) {
#pragma unroll
        for (int nt = 0; nt < NTN; nt++) {
            int row = bm + wm + mt * 16 + (lane >> 2);
            int col = bn + wn + nt * 8 + (lane & 3) * 2;
            float b0 = (z == 0) ? bias[col] : 0.f;
            float b1 = (z == 0) ? bias[col + 1] : 0.f;
            float v0 = acc[mt][nt][0] + b0, v1 = acc[mt][nt][1] + b1;
            float v2 = acc[mt][nt][2] + b0, v3 = acc[mt][nt][3] + b1;
            if (dorelu) {
                v0 = fmaxf(v0, 0.f); v1 = fmaxf(v1, 0.f);
                v2 = fmaxf(v2, 0.f); v3 = fmaxf(v3, 0.f);
            }
            if (Cz) {
                *(float2*)&Cz[(size_t)row * N + col] = make_float2(v0, v1);
                *(float2*)&Cz[(size_t)(row + 8) * N + col] = make_float2(v2, v3);
            }
            if (Ch) {
                *(__half2*)&Ch[(size_t)row * N + col] = __floats2half2_rn(v0, v1);
                *(__half2*)&Ch[(size_t)(row + 8) * N + col] = __floats2half2_rn(v2, v3);
            }
        }
    }
}

// ---------------- fp32 -> fp16 weights ----------------
__global__ void convB_kernel(const float* __restrict__ s, __half* __restrict__ o, int n4)
{
    int i = blockIdx.x * blockDim.x + threadIdx.x;
    if (i >= n4) return;
    float4 v = ((const float4*)s)[i];
    ((__half2*)o)[2 * i]     = __floats2half2_rn(v.x, v.y);
    ((__half2*)o)[2 * i + 1] = __floats2half2_rn(v.z, v.w);
}

// ---------------- embedding gather ----------------
__global__ __launch_bounds__(256) void embed_kernel(
    const int* __restrict__ caps, const float* __restrict__ Win,
    const float* __restrict__ bin, const float* __restrict__ pos,
    float* __restrict__ x, __half* __restrict__ xh)
{
    int n = blockIdx.x;
    int tok = caps[n];
    int l = n % SEQ;
#pragma unroll
    for (int e = threadIdx.x; e < EDIM; e += 256) {
        float v = Win[(size_t)e * VOC + tok] + bin[e] + pos[l * EDIM + e];
        x[(size_t)n * EDIM + e] = v;
        xh[(size_t)n * EDIM + e] = __float2half_rn(v);
    }
}

// ---------------- causal self-attention: 4 q-quarters, masked-dot skip, PDL -------
__global__ __launch_bounds__(256) void attn_kernel(const float* __restrict__ qkv,
                                                   __half* __restrict__ out)
{
    gdc_launch();
    gdc_wait();
    int bh = blockIdx.x >> 2, quarter = blockIdx.x & 3;
    int b = bh >> 3, h = bh & 7;
    const int kmax = (quarter + 1) * 20;
    __shared__ float Kt[80 * 65];
    __shared__ float Vs[80 * 64];
    __shared__ float pr[8 * 80];
    const float* base = qkv + (size_t)b * SEQ * 3 * EDIM;
    for (int i = threadIdx.x; i < kmax * 64; i += 256) {
        int t = i >> 6, d = i & 63;
        Kt[t * 65 + d] = base[t * 1536 + 512 + h * 64 + d];
        Vs[i]          = base[t * 1536 + 1024 + h * 64 + d];
    }
    __syncthreads();
    int warp = threadIdx.x >> 5, lane = threadIdx.x & 31;
    const bool need1 = kmax > 32;   // block-uniform: j1 in [32,64) can be live
    const bool need2 = kmax > 64;   // block-uniform: j2 in [64,80) can be live
    for (int qi = warp; qi < 20; qi += 8) {
        int q = quarter * 20 + qi;
        const float4* qrow = (const float4*)(base + q * 1536 + h * 64);
        int j0 = lane, j1 = lane + 32, j2 = lane + 64;
        const float* k0 = &Kt[j0 * 65];
        const float* k1 = &Kt[(j1 < 80 ? j1 : 0) * 65];
        const float* k2 = &Kt[(j2 < 80 ? j2 : 0) * 65];
        float a0 = 0.f, a1 = 0.f, a2 = 0.f;
        if (need2) {
#pragma unroll
            for (int kk = 0; kk < 16; kk++) {
                float4 qv = qrow[kk];
                int kb = kk * 4;
                a0 += qv.x * k0[kb] + qv.y * k0[kb + 1] + qv.z * k0[kb + 2] + qv.w * k0[kb + 3];
                a1 += qv.x * k1[kb] + qv.y * k1[kb + 1] + qv.z * k1[kb + 2] + qv.w * k1[kb + 3];
                a2 += qv.x * k2[kb] + qv.y * k2[kb + 1] + qv.z * k2[kb + 2] + qv.w * k2[kb + 3];
            }
        } else if (need1) {
#pragma unroll
            for (int kk = 0; kk < 16; kk++) {
                float4 qv = qrow[kk];
                int kb = kk * 4;
                a0 += qv.x * k0[kb] + qv.y * k0[kb + 1] + qv.z * k0[kb + 2] + qv.w * k0[kb + 3];
                a1 += qv.x * k1[kb] + qv.y * k1[kb + 1] + qv.z * k1[kb + 2] + qv.w * k1[kb + 3];
            }
        } else {
#pragma unroll
            for (int kk = 0; kk < 16; kk++) {
                float4 qv = qrow[kk];
                int kb = kk * 4;
                a0 += qv.x * k0[kb] + qv.y * k0[kb + 1] + qv.z * k0[kb + 2] + qv.w * k0[kb + 3];
            }
        }
        float s0 = (j0 <= q) ? a0 * 0.125f : -1e30f;
        float s1 = (j1 <= q) ? a1 * 0.125f : -1e30f;
        float s2 = (j2 <= q) ? a2 * 0.125f : -1e30f;
        float m = fmaxf(fmaxf(s0, s1), s2);
#pragma unroll
        for (int o = 16; o; o >>= 1) m = fmaxf(m, __shfl_xor_sync(0xffffffffu, m, o));
        float p0 = (j0 <= q) ? __expf(s0 - m) : 0.f;
        float p1 = (j1 <= q) ? __expf(s1 - m) : 0.f;
        float p2 = (j2 <= q) ? __expf(s2 - m) : 0.f;
        float sum = p0 + p1 + p2;
#pragma unroll
        for (int o = 16; o; o >>= 1) sum += __shfl_xor_sync(0xffffffffu, sum, o);
        float inv = 1.f / sum;
        pr[warp * 80 + j0] = p0 * inv;
        if (j1 < 80) pr[warp * 80 + j1] = p1 * inv;
        if (j2 < 80) pr[warp * 80 + j2] = p2 * inv;
        __syncwarp();
        float o0 = 0.f, o1 = 0.f;
#pragma unroll 10
        for (int j = 0; j < kmax; j++) {
            float pv = pr[warp * 80 + j];
            o0 += pv * Vs[j * 64 + lane];
            o1 += pv * Vs[j * 64 + 32 + lane];
        }
        out[(size_t)(b * 80 + q) * EDIM + h * 64 + lane] = __float2half_rn(o0);
        out[(size_t)(b * 80 + q) * EDIM + h * 64 + 32 + lane] = __float2half_rn(o1);
        __syncwarp();
    }
}

// ---------------- per-row stats helpers ----------------
__device__ __forceinline__ float2 row_stats(float v0, float v1, float v2, float v3,
                                            float* rs, float* rss, int tid)
{
    float s = v0 + v1 + v2 + v3;
    float ss = v0 * v0 + v1 * v1 + v2 * v2 + v3 * v3;
#pragma unroll
    for (int o = 16; o; o >>= 1) {
        s  += __shfl_xor_sync(0xffffffffu, s, o);
        ss += __shfl_xor_sync(0xffffffffu, ss, o);
    }
    int wid = tid >> 5;
    if ((tid & 31) == 0) { rs[wid] = s; rss[wid] = ss; }
    __syncthreads();
    int base = (tid >> 7) * 4;
    float tots  = rs[base]  + rs[base + 1]  + rs[base + 2]  + rs[base + 3];
    float totss = rss[base] + rss[base + 1] + rss[base + 2] + rss[base + 3];
    float mean = tots * (1.f / 512.f);
    float var = totss * (1.f / 512.f) - mean * mean;
    return make_float2(mean, rsqrtf(var + 1e-5f));
}
__device__ __forceinline__ void st_half4(__half* p, float o0, float o1, float o2, float o3)
{
    __half2 h01 = __floats2half2_rn(o0, o1), h23 = __floats2half2_rn(o2, o3);
    uint2 u;
    u.x = *(uint32_t*)&h01; u.y = *(uint32_t*)&h23;
    *(uint2*)p = u;
}

// ---------------- x = LN(x + a0+a1+a2); PDL ----------------
__global__ __launch_bounds__(256) void add_ln_kernel(
    float* __restrict__ x, __half* __restrict__ xh, const float* __restrict__ add,
    const float* __restrict__ w, const float* __restrict__ b, int writeX)
{
    gdc_launch();
    gdc_wait();
    __shared__ float rs[8], rss[8];
    int tid = threadIdx.x, tt = tid & 127;
    const size_t P = (size_t)NTOK * EDIM;
    size_t off = (size_t)(blockIdx.x * 2 + (tid >> 7)) * EDIM + tt * 4;
    float4 xv = *(const float4*)&x[off];
    float4 a0 = *(const float4*)&add[off];
    float4 a1 = *(const float4*)&add[P + off];
    float4 a2 = *(const float4*)&add[2 * P + off];
    float v0 = xv.x + a0.x + a1.x + a2.x, v1 = xv.y + a0.y + a1.y + a2.y;
    float v2 = xv.z + a0.z + a1.z + a2.z, v3 = xv.w + a0.w + a1.w + a2.w;
    float2 mi = row_stats(v0, v1, v2, v3, rs, rss, tid);
    int c = tt * 4;
    float4 wv = *(const float4*)&w[c], bv = *(const float4*)&b[c];
    float o0 = (v0 - mi.x) * mi.y * wv.x + bv.x;
    float o1 = (v1 - mi.x) * mi.y * wv.y + bv.y;
    float o2 = (v2 - mi.x) * mi.y * wv.z + bv.z;
    float o3 = (v3 - mi.x) * mi.y * wv.w + bv.w;
    if (writeX) *(float4*)&x[off] = make_float4(o0, o1, o2, o3);
    st_half4(&xh[off], o0, o1, o2, o3);
}

// ---------------- fused ln1 + cvec + ln2; PDL ----------------
__global__ __launch_bounds__(256) void add_ln2_kernel(
    float* __restrict__ x, __half* __restrict__ xh, const float* __restrict__ add,
    const float* __restrict__ cv,
    const float* __restrict__ w1, const float* __restrict__ b1,
    const float* __restrict__ w2, const float* __restrict__ b2)
{
    gdc_launch();
    gdc_wait();
    __shared__ float rs[8], rss[8];
    int tid = threadIdx.x, tt = tid & 127;
    const size_t P = (size_t)NTOK * EDIM;
    size_t off = (size_t)(blockIdx.x * 2 + (tid >> 7)) * EDIM + tt * 4;
    float4 xv = *(const float4*)&x[off];
    float4 a0 = *(const float4*)&add[off];
    float4 a1 = *(const float4*)&add[P + off];
    float4 a2 = *(const float4*)&add[2 * P + off];
    float v0 = xv.x + a0.x + a1.x + a2.x, v1 = xv.y + a0.y + a1.y + a2.y;
    float v2 = xv.z + a0.z + a1.z + a2.z, v3 = xv.w + a0.w + a1.w + a2.w;
    float2 mi = row_stats(v0, v1, v2, v3, rs, rss, tid);
    int c = tt * 4;
    float4 wv = *(const float4*)&w1[c], bv = *(const float4*)&b1[c];
    float4 cvv = *(const float4*)&cv[c];
    float y0 = (v0 - mi.x) * mi.y * wv.x + bv.x + cvv.x;
    float y1 = (v1 - mi.x) * mi.y * wv.y + bv.y + cvv.y;
    float y2 = (v2 - mi.x) * mi.y * wv.z + bv.z + cvv.z;
    float y3 = (v3 - mi.x) * mi.y * wv.w + bv.w + cvv.w;
    __syncthreads();
    mi = row_stats(y0, y1, y2, y3, rs, rss, tid);
    wv = *(const float4*)&w2[c]; bv = *(const float4*)&b2[c];
    float o0 = (y0 - mi.x) * mi.y * wv.x + bv.x;
    float o1 = (y1 - mi.x) * mi.y * wv.y + bv.y;
    float o2 = (y2 - mi.x) * mi.y * wv.z + bv.z;
    float o3 = (y3 - mi.x) * mi.y * wv.w + bv.w;
    *(float4*)&x[off] = make_float4(o0, o1, o2, o3);
    st_half4(&xh[off], o0, o1, o2, o3);
}

// ---------------- all-layer cross-attn constant vectors ----------------
__global__ void ca_const_kernel(const float* __restrict__ ow, const float* __restrict__ ib,
                                const float* __restrict__ ob, float* __restrict__ c)
{
    int gw = (blockIdx.x * blockDim.x + threadIdx.x) >> 5;
    int lane = threadIdx.x & 31;
    if (gw >= NLAYER * EDIM) return;
    int layer = gw >> 9, e = gw & 511;
    const float* owl = ow + (size_t)layer * EDIM * EDIM + (size_t)e * EDIM;
    const float* vb = ib + (size_t)layer * 3 * EDIM + 2 * EDIM;
    float s = 0.f;
#pragma unroll
    for (int f = lane; f < EDIM; f += 32) s += owl[f] * vb[f];
#pragma unroll
    for (int o = 16; o; o >>= 1) s += __shfl_xor_sync(0xffffffffu, s, o);
    if (lane == 0) c[gw] = ob[gw] + s;
}

// ---------------- PDL launch helper ----------------
template <typename F, typename... Args>
static void launch_pdl(F kern, dim3 grid, dim3 block, size_t smem, Args... args)
{
    cudaLaunchConfig_t cfg = {};
    cfg.gridDim = grid;
    cfg.blockDim = block;
    cfg.dynamicSmemBytes = smem;
    cfg.stream = 0;
    cudaLaunchAttribute attr[1];
    attr[0].id = cudaLaunchAttributeProgrammaticStreamSerialization;
    attr[0].val.programmaticStreamSerializationAllowed = 1;
    cfg.attrs = attr;
    cfg.numAttrs = 1;
    cudaLaunchKernelEx(&cfg, kern, args...);
}

// ---------------- launch ----------------
extern "C" void kernel_launch(void* const* d_in, const int* in_sizes, int n_in,
                              void* d_out, int out_size)
{
    const int*   caps    = (const int*)  d_in[0];
    const float* W_in    = (const float*)d_in[1];
    const float* b_in    = (const float*)d_in[2];
    const float* pos_emb = (const float*)d_in[3];
    const float* sa_in_w  = (const float*)d_in[4];
    const float* sa_in_b  = (const float*)d_in[5];
    const float* sa_out_w = (const float*)d_in[6];
    const float* sa_out_b = (const float*)d_in[7];
    const float* ca_in_b  = (const float*)d_in[9];
    const float* ca_out_w = (const float*)d_in[10];
    const float* ca_out_b = (const float*)d_in[11];
    const float* ff1_w = (const float*)d_in[12];
    const float* ff1_b = (const float*)d_in[13];
    const float* ff2_w = (const float*)d_in[14];
    const float* ff2_b = (const float*)d_in[15];
    const float* ln1_w = (const float*)d_in[16];
    const float* ln1_b = (const float*)d_in[17];
    const float* ln2_w = (const float*)d_in[18];
    const float* ln2_b = (const float*)d_in[19];
    const float* ln3_w = (const float*)d_in[20];
    const float* ln3_b = (const float*)d_in[21];
    const float* out_w = (const float*)d_in[22];
    const float* out_b = (const float*)d_in[23];

    float *x, *qkv, *t512, *cvec;
    __half *xh, *t512h, *h1h, *wsain, *wsaout, *wff1, *wff2, *wout;
    cudaGetSymbolAddress((void**)&x, g_x);
    cudaGetSymbolAddress((void**)&qkv, g_qkv);
    cudaGetSymbolAddress((void**)&t512, g_t512);
    cudaGetSymbolAddress((void**)&cvec, g_c);
    cudaGetSymbolAddress((void**)&xh, g_xh);
    cudaGetSymbolAddress((void**)&t512h, g_t512h);
    cudaGetSymbolAddress((void**)&h1h, g_h1h);
    cudaGetSymbolAddress((void**)&wsain, g_wsain);
    cudaGetSymbolAddress((void**)&wsaout, g_wsaout);
    cudaGetSymbolAddress((void**)&wff1, g_wff1);
    cudaGetSymbolAddress((void**)&wff2, g_wff2);
    cudaGetSymbolAddress((void**)&wout, g_wout);

    cudaFuncSetAttribute(gemm_k, cudaFuncAttributeMaxDynamicSharedMemorySize, SMEM_G);

    cudaStream_t s2;
    cudaStreamCreateWithFlags(&s2, cudaStreamNonBlocking);
    cudaEvent_t eFork, eSain, eCa, eSaout, eFf1, eFf2, eWout;
    cudaEventCreateWithFlags(&eFork, cudaEventDisableTiming);
    cudaEventCreateWithFlags(&eSain, cudaEventDisableTiming);
    cudaEventCreateWithFlags(&eCa, cudaEventDisableTiming);
    cudaEventCreateWithFlags(&eSaout, cudaEventDisableTiming);
    cudaEventCreateWithFlags(&eFf1, cudaEventDisableTiming);
    cudaEventCreateWithFlags(&eFf2, cudaEventDisableTiming);
    cudaEventCreateWithFlags(&eWout, cudaEventDisableTiming);

    auto convOn = [&](cudaStream_t st, const float* src, __half* dst, size_t nelem) {
        int n4 = (int)(nelem / 4);
        convB_kernel<<<(n4 + 255) / 256, 256, 0, st>>>(src, dst, n4);
    };
    auto gemm = [&](const __half* Aw, const __half* Bw, const float* bias,
                    float* C, __half* Ch, int M, int N, int ldk, int ksp, int K,
                    size_t csplit, int relu) {
        int nz = (K + ksp - 1) / ksp;
        launch_pdl(gemm_k, dim3(M / 128, N / 128, nz), dim3(256), (size_t)SMEM_G,
                   Aw, Bw, bias, C, Ch, M, N, ldk, ksp, K, csplit, relu);
    };

    cudaEventRecord(eFork, 0);
    cudaStreamWaitEvent(s2, eFork, 0);

    embed_kernel<<<NTOK, 256>>>(caps, W_in, b_in, pos_emb, x, xh);
    convOn(s2, sa_in_w, wsain, (size_t)NLAYER * 3 * EDIM * EDIM);
    cudaEventRecord(eSain, s2);
    ca_const_kernel<<<256, 256, 0, s2>>>(ca_out_w, ca_in_b, ca_out_b, cvec);
    cudaEventRecord(eCa, s2);
    convOn(s2, sa_out_w, wsaout, (size_t)NLAYER * EDIM * EDIM);
    cudaEventRecord(eSaout, s2);
    convOn(s2, ff1_w, wff1, (size_t)NLAYER * FFD * EDIM);
    cudaEventRecord(eFf1, s2);

    cudaStreamWaitEvent(0, eSain, 0);
    const size_t CS = (size_t)NTOK * EDIM;
    gemm(xh, wsain, sa_in_b, qkv, nullptr, NTOK, 3 * EDIM, EDIM, EDIM, EDIM, 0, 0);

    convOn(s2, ff2_w, wff2, (size_t)NLAYER * EDIM * FFD);
    cudaEventRecord(eFf2, s2);
    convOn(s2, out_w, wout, (size_t)VOC * EDIM);
    cudaEventRecord(eWout, s2);

    for (int i = 0; i < NLAYER; i++) {
        if (i > 0)
            gemm(xh, wsain + (size_t)i * 3 * EDIM * EDIM, sa_in_b + (size_t)i * 3 * EDIM,
                 qkv, nullptr, NTOK, 3 * EDIM, EDIM, EDIM, EDIM, 0, 0);
        launch_pdl(attn_kernel, dim3(32 * NHEAD * 4), dim3(256), (size_t)0,
                   (const float*)qkv, (__half*)t512h);
        if (i == 0) cudaStreamWaitEvent(0, eSaout, 0);
        gemm(t512h, wsaout + (size_t)i * EDIM * EDIM, sa_out_b + (size_t)i * EDIM,
             t512, nullptr, NTOK, EDIM, EDIM, 192, EDIM, CS, 0);
        if (i == 0) cudaStreamWaitEvent(0, eCa, 0);
        launch_pdl(add_ln2_kernel, dim3(NTOK / 2), dim3(256), (size_t)0,
                   x, xh, (const float*)t512, (const float*)(cvec + i * EDIM),
                   ln1_w + i * EDIM, ln1_b + i * EDIM,
                   ln2_w + i * EDIM, ln2_b + i * EDIM);
        if (i == 0) cudaStreamWaitEvent(0, eFf1, 0);
        gemm(xh, wff1 + (size_t)i * FFD * EDIM, ff1_b + (size_t)i * FFD,
             nullptr, h1h, NTOK, FFD, EDIM, EDIM, EDIM, 0, 1);
        if (i == 0) cudaStreamWaitEvent(0, eFf2, 0);
        gemm(h1h, wff2 + (size_t)i * EDIM * FFD, ff2_b + (size_t)i * EDIM,
             t512, nullptr, NTOK, EDIM, FFD, 704, FFD, CS, 0);
        launch_pdl(add_ln_kernel, dim3(NTOK / 2), dim3(256), (size_t)0,
                   x, xh, (const float*)t512,
                   ln3_w + i * EDIM, ln3_b + i * EDIM, (int)(i < NLAYER - 1));
    }

    cudaStreamWaitEvent(0, eWout, 0);
    gemm(xh, wout, out_b, (float*)d_out, nullptr, NTOK, VOC, EDIM, EDIM, EDIM, 0, 0);
}